// round 10
// baseline (speedup 1.0000x reference)
#include <cuda_runtime.h>
#include <cstdint>
#include <cstddef>

#define S_LEN 8192
#define HID   1024
#define G4    4096   // 4*HID

// ---------------- scratch (device globals: allocation-free) ----------------
// gates layout: [S][HID][4]  (4 gate values for hidden j contiguous)
__device__ float g_gates[(size_t)S_LEN * G4];   // 128 MB
__device__ float g_yA[(size_t)S_LEN * HID];     // 32 MB: layer outputs ping
__device__ float g_yB[(size_t)S_LEN * HID];     // 32 MB: layer outputs pong
// tagged hidden state: ONE u64 per (parity, j): {tag:u32 | value:f32}.
// Scalar aligned 8B accesses are single-copy atomic per the PTX memory model
// (vector v2/v4 are NOT — they decompose into independent component accesses).
__device__ __align__(8) unsigned long long g_hx[2 * HID];

// ---------------- packed f32x2 helpers (sm_103a FFMA2) ----------------
__device__ __forceinline__ void ffma2(unsigned long long& d,
                                      unsigned long long a,
                                      unsigned long long b) {
    asm("fma.rn.f32x2 %0, %1, %2, %0;" : "+l"(d) : "l"(a), "l"(b));
}
__device__ __forceinline__ unsigned long long pack2(float x, float y) {
    unsigned long long r;
    asm("mov.b64 %0, {%1, %2};" : "=l"(r)
        : "r"(__float_as_uint(x)), "r"(__float_as_uint(y)));
    return r;
}
__device__ __forceinline__ float2 unpack2(unsigned long long v) {
    unsigned int lo, hi;
    asm("mov.b64 {%0, %1}, %2;" : "=r"(lo), "=r"(hi) : "l"(v));
    float2 r; r.x = __uint_as_float(lo); r.y = __uint_as_float(hi);
    return r;
}

__device__ __forceinline__ float sigmoidf_(float x) {
    return __fdividef(1.0f, 1.0f + __expf(-x));
}
// fast, overflow-safe tanh: tanh(x) = sign(x) * (1-e)/(1+e), e = exp(-2|x|)
__device__ __forceinline__ float tanhf_(float x) {
    float e = __expf(-2.0f * fabsf(x));
    float r = __fdividef(1.0f - e, 1.0f + e);
    return copysignf(r, x);
}

// single-copy-atomic 8B publish/poll (L2 scope, volatile: no CSE/hoist)
__device__ __forceinline__ unsigned long long ldcg8(const unsigned long long* p) {
    unsigned long long r;
    asm volatile("ld.global.cg.u64 %0, [%1];" : "=l"(r) : "l"(p));
    return r;
}
__device__ __forceinline__ void stcg8(unsigned long long* p, unsigned long long v) {
    asm volatile("st.global.cg.u64 [%0], %1;" :: "l"(p), "l"(v) : "memory");
}

// ---------------- GEMM: gates[S][HID][4] = X[S,K] @ W[4H,K]^T + b ----------
// BM=BN=128, BK=16, 256 threads, 8x8 microtile, f32x2 packed FMAs.
__global__ __launch_bounds__(256)
void gemm_xwt(const float* __restrict__ Xext, int xsel,
              const float* __restrict__ W, const float* __restrict__ bias,
              int K)
{
    const float* X = (xsel == 0) ? Xext : (xsel == 1 ? g_yA : g_yB);

    __shared__ float a_s[16][128];
    __shared__ float b_s[16][128];

    const int tid = threadIdx.x;
    const int bm = blockIdx.y * 128;
    const int bn = blockIdx.x * 128;
    const int tx = tid & 15;   // 0..15 -> N
    const int ty = tid >> 4;   // 0..15 -> M

    unsigned long long acc[8][4];
#pragma unroll
    for (int i = 0; i < 8; ++i)
#pragma unroll
        for (int jp = 0; jp < 4; ++jp) acc[i][jp] = 0ull;

    for (int k0 = 0; k0 < K; k0 += 16) {
#pragma unroll
        for (int r = 0; r < 2; ++r) {
            int q   = tid + r * 256;      // 0..511 float4 slots
            int row = q >> 2;             // 0..127
            int kq  = (q & 3) << 2;       // 0,4,8,12
            float4 va = *(const float4*)(X + (size_t)(bm + row) * K + k0 + kq);
            a_s[kq + 0][row] = va.x; a_s[kq + 1][row] = va.y;
            a_s[kq + 2][row] = va.z; a_s[kq + 3][row] = va.w;
            float4 vb = *(const float4*)(W + (size_t)(bn + row) * K + k0 + kq);
            b_s[kq + 0][row] = vb.x; b_s[kq + 1][row] = vb.y;
            b_s[kq + 2][row] = vb.z; b_s[kq + 3][row] = vb.w;
        }
        __syncthreads();
#pragma unroll
        for (int kk = 0; kk < 16; ++kk) {
            float4 a0 = *(const float4*)&a_s[kk][ty * 8];
            float4 a1 = *(const float4*)&a_s[kk][ty * 8 + 4];
            float4 b0 = *(const float4*)&b_s[kk][tx * 8];
            float4 b1 = *(const float4*)&b_s[kk][tx * 8 + 4];
            unsigned long long bp0 = pack2(b0.x, b0.y);
            unsigned long long bp1 = pack2(b0.z, b0.w);
            unsigned long long bp2 = pack2(b1.x, b1.y);
            unsigned long long bp3 = pack2(b1.z, b1.w);
            float av[8] = {a0.x, a0.y, a0.z, a0.w, a1.x, a1.y, a1.z, a1.w};
#pragma unroll
            for (int i = 0; i < 8; ++i) {
                unsigned long long ap = pack2(av[i], av[i]);
                ffma2(acc[i][0], ap, bp0);
                ffma2(acc[i][1], ap, bp1);
                ffma2(acc[i][2], ap, bp2);
                ffma2(acc[i][3], ap, bp3);
            }
        }
        __syncthreads();
    }

    // epilogue: scatter into [S][HID][4] interleaved-gate layout
    const int gate = bn >> 10;          // constant per block (bn multiple of 128)
#pragma unroll
    for (int i = 0; i < 8; ++i) {
        size_t row = (size_t)(bm + ty * 8 + i);
#pragma unroll
        for (int jp = 0; jp < 4; ++jp) {
            int col = bn + tx * 8 + jp * 2;
            int jj  = col - (gate << 10);
            float2 v = unpack2(acc[i][jp]);
            g_gates[row * G4 + (size_t)jj * 4 + gate]       = v.x + bias[col];
            g_gates[row * G4 + (size_t)(jj + 1) * 4 + gate] = v.y + bias[col + 1];
        }
    }
}

// ---------------- persistent recurrent scan (one launch per layer) ---------
// 128 blocks x 8 warps; warp w of block b owns hidden index j = b*8+w and
// computes all 4 gate rows for j. w_hh in registers (128 fp32/lane).
//
// Inter-SM sync = tagged-h dataflow staged through SMEM, two-phase:
//   poll pair A (both u64s in flight) -> wait -> stage h[0:512]
//   -> issue pair-B polls (fresh: phase-A readiness implies the publish
//      wave happened) -> bar -> GEMV half0 (overlaps B round trip)
//   -> check B (usually ready: no sleep) -> stage h[512:1024] -> bar
//   -> GEMV half1 -> reduce -> epilogue -> publish
// Wait loops keep the VALIDATED unconditional nanosleep(40) backoff as the
// fallback; the design minimizes how often a sleep segment is actually paid.
__global__ __launch_bounds__(256, 1)
void lstm_scan(const float* __restrict__ w_hh, int ysel, int layer)
{
    float* y_out = (ysel == 1) ? g_yA : g_yB;

    __shared__ __align__(16) float sm_h[2][HID];   // double-buffered staged h

    const int tid  = threadIdx.x;
    const int lane = tid & 31;
    const int warp = tid >> 5;
    const int j    = blockIdx.x * 8 + warp;    // 0..1023
    const unsigned tagbase = (unsigned)(layer * S_LEN + 1);  // never 0

    // this warp's w_hh slice in registers: w[gate][it] covers
    // k = it*128 + lane*4 .. +3, packed as two f32x2.
    unsigned long long w[4][8][2];
#pragma unroll
    for (int g = 0; g < 4; ++g)
#pragma unroll
        for (int it = 0; it < 8; ++it) {
            union { float4 f4; unsigned long long u[2]; } t;
            t.f4 = *(const float4*)(w_hh + (size_t)(g * HID + j) * HID
                                    + it * 128 + lane * 4);
            w[g][it][0] = t.u[0];
            w[g][it][1] = t.u[1];
        }

    float c = 0.0f;  // cell state (redundant in all lanes)

    // gates prefetch pipeline, 2 steps deep. Warp-uniform float4 load:
    // every lane gets all 4 gate values for its j (same 16B sector).
    const float4* gbase = (const float4*)g_gates + j;   // stride G4/4 per step
    float4 gq  = __ldcg(gbase + (size_t)0 * HID);
    float4 gq1 = __ldcg(gbase + (size_t)1 * HID);

    for (int t = 0; t < S_LEN; ++t) {
        // prefetch gates for t+2
        float4 gq2 = make_float4(0.f, 0.f, 0.f, 0.f);
        if (t + 2 < S_LEN) gq2 = __ldcg(gbase + (size_t)(t + 2) * HID);

        const int par = (t - 1) & 1;
        const unsigned tb = tagbase + (unsigned)(t - 1);
        // thread tid stages j = 2*tid and j = 2*tid+1 per phase
        const unsigned long long* pA0 = g_hx + par * HID + 2 * tid;
        const unsigned long long* pB0 = pA0 + 512;

        unsigned long long a0 = 0, a1 = 0, a2 = 0, a3 = 0;
        unsigned long long s0 = 0, s1 = 0;

        if (t > 0) {
            // ---- phase A: both polls in flight, then wait ---------------
            unsigned long long r0 = ldcg8(pA0);
            unsigned long long r1 = ldcg8(pA0 + 1);
            while ((unsigned)(r0 >> 32) != tb) { __nanosleep(40); r0 = ldcg8(pA0); }
            while ((unsigned)(r1 >> 32) != tb) { __nanosleep(40); r1 = ldcg8(pA0 + 1); }
            sm_h[par][2 * tid]     = __uint_as_float((unsigned)r0);
            sm_h[par][2 * tid + 1] = __uint_as_float((unsigned)r1);
            // ---- issue phase-B polls NOW (publish wave already happened;
            //      round trip overlaps the bar + GEMV half0 below) --------
            s0 = ldcg8(pB0);
            s1 = ldcg8(pB0 + 1);
        }
        __syncthreads();

        if (t > 0) {
            // ---- GEMV half0 (k = 0..511) while phase-B polls fly --------
            const float* hs = sm_h[par];
#pragma unroll
            for (int it = 0; it < 4; ++it) {
                union { float4 f4; unsigned long long u[2]; } hv;
                hv.f4 = *(const float4*)(hs + it * 128 + lane * 4);
                ffma2(a0, hv.u[0], w[0][it][0]); ffma2(a0, hv.u[1], w[0][it][1]);
                ffma2(a1, hv.u[0], w[1][it][0]); ffma2(a1, hv.u[1], w[1][it][1]);
                ffma2(a2, hv.u[0], w[2][it][0]); ffma2(a2, hv.u[1], w[2][it][1]);
                ffma2(a3, hv.u[0], w[3][it][0]); ffma2(a3, hv.u[1], w[3][it][1]);
            }
            // ---- phase B: check the in-flight polls (sleep = fallback) --
            while ((unsigned)(s0 >> 32) != tb) { __nanosleep(40); s0 = ldcg8(pB0); }
            while ((unsigned)(s1 >> 32) != tb) { __nanosleep(40); s1 = ldcg8(pB0 + 1); }
            sm_h[par][512 + 2 * tid] = __uint_as_float((unsigned)s0);
            sm_h[par][513 + 2 * tid] = __uint_as_float((unsigned)s1);
        }
        __syncthreads();

        if (t > 0) {
            // ---- GEMV half1 (k = 512..1023) ----
            const float* hs = sm_h[par];
#pragma unroll
            for (int it = 4; it < 8; ++it) {
                union { float4 f4; unsigned long long u[2]; } hv;
                hv.f4 = *(const float4*)(hs + it * 128 + lane * 4);
                ffma2(a0, hv.u[0], w[0][it][0]); ffma2(a0, hv.u[1], w[0][it][1]);
                ffma2(a1, hv.u[0], w[1][it][0]); ffma2(a1, hv.u[1], w[1][it][1]);
                ffma2(a2, hv.u[0], w[2][it][0]); ffma2(a2, hv.u[1], w[2][it][1]);
                ffma2(a3, hv.u[0], w[3][it][0]); ffma2(a3, hv.u[1], w[3][it][1]);
            }
        }

        float2 p;
        p = unpack2(a0); float si = p.x + p.y;
        p = unpack2(a1); float sf = p.x + p.y;
        p = unpack2(a2); float sg = p.x + p.y;
        p = unpack2(a3); float so = p.x + p.y;
#pragma unroll
        for (int off = 16; off; off >>= 1) {
            si += __shfl_xor_sync(0xffffffffu, si, off);
            sf += __shfl_xor_sync(0xffffffffu, sf, off);
            sg += __shfl_xor_sync(0xffffffffu, sg, off);
            so += __shfl_xor_sync(0xffffffffu, so, off);
        }
        // butterfly left full sums in every lane; all lanes compute the
        // epilogue redundantly (no broadcast shuffles on the chain)
        float i_  = sigmoidf_(si + gq.x);
        float f_  = sigmoidf_(sf + gq.y);
        float gg_ = tanhf_  (sg + gq.z);
        float o_  = sigmoidf_(so + gq.w);
        c = f_ * c + i_ * gg_;
        float hn = o_ * tanhf_(c);
        if (lane == 0) {
            // publish {tag|value} as ONE atomic u64 — the inter-SM sync
            unsigned long long pub =
                ((unsigned long long)(tagbase + (unsigned)t) << 32)
                | (unsigned long long)__float_as_uint(hn);
            stcg8(&g_hx[(t & 1) * HID + j], pub);
            y_out[(size_t)t * HID + j] = hn;
        }
        gq = gq1; gq1 = gq2;
    }
}

// ---------------- final FC: out = h_last . fc_w + fc_b ---------------------
__global__ void fc_kernel(const float* __restrict__ w,
                          const float* __restrict__ b,
                          float* __restrict__ out)
{
    const float* h = g_yB + (size_t)(S_LEN - 1) * HID;
    const int tid = threadIdx.x;
    float s = 0.0f;
    for (int k = tid; k < HID; k += 256) s += h[k] * w[k];
#pragma unroll
    for (int off = 16; off; off >>= 1) s += __shfl_xor_sync(0xffffffffu, s, off);
    __shared__ float red[8];
    if ((tid & 31) == 0) red[tid >> 5] = s;
    __syncthreads();
    if (tid == 0) {
        float tot = 0.0f;
#pragma unroll
        for (int i = 0; i < 8; ++i) tot += red[i];
        out[0] = tot + b[0];
    }
}

// ---------------- launch ----------------------------------------------------
extern "C" void kernel_launch(void* const* d_in, const int* in_sizes, int n_in,
                              void* d_out, int out_size)
{
    (void)in_sizes; (void)n_in; (void)out_size;
    const float* seq   = (const float*)d_in[0];
    const float* w_ih0 = (const float*)d_in[1];
    const float* w_hh0 = (const float*)d_in[2];
    const float* b0    = (const float*)d_in[3];
    const float* w_ih1 = (const float*)d_in[4];
    const float* w_hh1 = (const float*)d_in[5];
    const float* b1    = (const float*)d_in[6];
    const float* w_ih2 = (const float*)d_in[7];
    const float* w_hh2 = (const float*)d_in[8];
    const float* b2    = (const float*)d_in[9];
    const float* w_ih3 = (const float*)d_in[10];
    const float* w_hh3 = (const float*)d_in[11];
    const float* b3    = (const float*)d_in[12];
    const float* fc_w  = (const float*)d_in[13];
    const float* fc_b  = (const float*)d_in[14];
    float* out = (float*)d_out;

    dim3 ggrid(G4 / 128, S_LEN / 128);

    // layer 0
    gemm_xwt<<<ggrid, 256>>>(seq, 0, w_ih0, b0, 256);
    lstm_scan<<<128, 256>>>(w_hh0, 1, 0);   // -> g_yA
    // layer 1
    gemm_xwt<<<ggrid, 256>>>(nullptr, 1, w_ih1, b1, HID);
    lstm_scan<<<128, 256>>>(w_hh1, 2, 1);   // -> g_yB
    // layer 2
    gemm_xwt<<<ggrid, 256>>>(nullptr, 2, w_ih2, b2, HID);
    lstm_scan<<<128, 256>>>(w_hh2, 1, 2);   // -> g_yA
    // layer 3
    gemm_xwt<<<ggrid, 256>>>(nullptr, 1, w_ih3, b3, HID);
    lstm_scan<<<128, 256>>>(w_hh3, 2, 3);   // -> g_yB
    // head
    fc_kernel<<<1, 256>>>(fc_w, fc_b, out);
}

// round 11
// speedup vs baseline: 2.2623x; 2.2623x over previous
#include <cuda_runtime.h>
#include <cstdint>
#include <cstddef>

#define S_LEN 8192
#define HID   1024
#define G4    4096   // 4*HID

// ---------------- scratch (device globals: allocation-free) ----------------
// gates layout: [S][HID][4]  (4 gate values for hidden j contiguous)
__device__ float g_gates[(size_t)S_LEN * G4];   // 128 MB
__device__ float g_yA[(size_t)S_LEN * HID];     // 32 MB: layer outputs ping
__device__ float g_yB[(size_t)S_LEN * HID];     // 32 MB: layer outputs pong
// tagged hidden state: ONE u64 per (parity, j): {tag:u32 | value:f32}.
// Scalar aligned 8B accesses are single-copy atomic per the PTX memory model.
// 16B-aligned so pairs can be polled with ld.v2.u64 (each 8B component is
// still atomic; decomposition can only split BETWEEN pairs, never inside).
__device__ __align__(16) unsigned long long g_hx[2 * HID];

// ---------------- packed f32x2 helpers (sm_103a FFMA2) ----------------
__device__ __forceinline__ void ffma2(unsigned long long& d,
                                      unsigned long long a,
                                      unsigned long long b) {
    asm("fma.rn.f32x2 %0, %1, %2, %0;" : "+l"(d) : "l"(a), "l"(b));
}
__device__ __forceinline__ unsigned long long pack2(float x, float y) {
    unsigned long long r;
    asm("mov.b64 %0, {%1, %2};" : "=l"(r)
        : "r"(__float_as_uint(x)), "r"(__float_as_uint(y)));
    return r;
}
__device__ __forceinline__ float2 unpack2(unsigned long long v) {
    unsigned int lo, hi;
    asm("mov.b64 {%0, %1}, %2;" : "=r"(lo), "=r"(hi) : "l"(v));
    float2 r; r.x = __uint_as_float(lo); r.y = __uint_as_float(hi);
    return r;
}

__device__ __forceinline__ float sigmoidf_(float x) {
    return __fdividef(1.0f, 1.0f + __expf(-x));
}
// fast, overflow-safe tanh: tanh(x) = sign(x) * (1-e)/(1+e), e = exp(-2|x|)
__device__ __forceinline__ float tanhf_(float x) {
    float e = __expf(-2.0f * fabsf(x));
    float r = __fdividef(1.0f - e, 1.0f + e);
    return copysignf(r, x);
}

// 16B poll of two tagged u64 pairs (L2 scope, volatile: no CSE/hoist)
__device__ __forceinline__ ulonglong2 ldcg16(const ulonglong2* p) {
    ulonglong2 v;
    asm volatile("ld.global.cg.v2.u64 {%0,%1}, [%2];"
                 : "=l"(v.x), "=l"(v.y) : "l"(p));
    return v;
}
__device__ __forceinline__ void stcg8(unsigned long long* p, unsigned long long v) {
    asm volatile("st.global.cg.u64 [%0], %1;" :: "l"(p), "l"(v) : "memory");
}

// ---------------- GEMM: gates[S][HID][4] = X[S,K] @ W[4H,K]^T + b ----------
// BM=BN=128, BK=16, 256 threads, 8x8 microtile, f32x2 packed FMAs.
__global__ __launch_bounds__(256)
void gemm_xwt(const float* __restrict__ Xext, int xsel,
              const float* __restrict__ W, const float* __restrict__ bias,
              int K)
{
    const float* X = (xsel == 0) ? Xext : (xsel == 1 ? g_yA : g_yB);

    __shared__ float a_s[16][128];
    __shared__ float b_s[16][128];

    const int tid = threadIdx.x;
    const int bm = blockIdx.y * 128;
    const int bn = blockIdx.x * 128;
    const int tx = tid & 15;   // 0..15 -> N
    const int ty = tid >> 4;   // 0..15 -> M

    unsigned long long acc[8][4];
#pragma unroll
    for (int i = 0; i < 8; ++i)
#pragma unroll
        for (int jp = 0; jp < 4; ++jp) acc[i][jp] = 0ull;

    for (int k0 = 0; k0 < K; k0 += 16) {
#pragma unroll
        for (int r = 0; r < 2; ++r) {
            int q   = tid + r * 256;      // 0..511 float4 slots
            int row = q >> 2;             // 0..127
            int kq  = (q & 3) << 2;       // 0,4,8,12
            float4 va = *(const float4*)(X + (size_t)(bm + row) * K + k0 + kq);
            a_s[kq + 0][row] = va.x; a_s[kq + 1][row] = va.y;
            a_s[kq + 2][row] = va.z; a_s[kq + 3][row] = va.w;
            float4 vb = *(const float4*)(W + (size_t)(bn + row) * K + k0 + kq);
            b_s[kq + 0][row] = vb.x; b_s[kq + 1][row] = vb.y;
            b_s[kq + 2][row] = vb.z; b_s[kq + 3][row] = vb.w;
        }
        __syncthreads();
#pragma unroll
        for (int kk = 0; kk < 16; ++kk) {
            float4 a0 = *(const float4*)&a_s[kk][ty * 8];
            float4 a1 = *(const float4*)&a_s[kk][ty * 8 + 4];
            float4 b0 = *(const float4*)&b_s[kk][tx * 8];
            float4 b1 = *(const float4*)&b_s[kk][tx * 8 + 4];
            unsigned long long bp0 = pack2(b0.x, b0.y);
            unsigned long long bp1 = pack2(b0.z, b0.w);
            unsigned long long bp2 = pack2(b1.x, b1.y);
            unsigned long long bp3 = pack2(b1.z, b1.w);
            float av[8] = {a0.x, a0.y, a0.z, a0.w, a1.x, a1.y, a1.z, a1.w};
#pragma unroll
            for (int i = 0; i < 8; ++i) {
                unsigned long long ap = pack2(av[i], av[i]);
                ffma2(acc[i][0], ap, bp0);
                ffma2(acc[i][1], ap, bp1);
                ffma2(acc[i][2], ap, bp2);
                ffma2(acc[i][3], ap, bp3);
            }
        }
        __syncthreads();
    }

    // epilogue: scatter into [S][HID][4] interleaved-gate layout
    const int gate = bn >> 10;          // constant per block (bn multiple of 128)
#pragma unroll
    for (int i = 0; i < 8; ++i) {
        size_t row = (size_t)(bm + ty * 8 + i);
#pragma unroll
        for (int jp = 0; jp < 4; ++jp) {
            int col = bn + tx * 8 + jp * 2;
            int jj  = col - (gate << 10);
            float2 v = unpack2(acc[i][jp]);
            g_gates[row * G4 + (size_t)jj * 4 + gate]       = v.x + bias[col];
            g_gates[row * G4 + (size_t)(jj + 1) * 4 + gate] = v.y + bias[col + 1];
        }
    }
}

// ---------------- persistent recurrent scan (one launch per layer) ---------
// 128 blocks x 8 warps; warp w of block b owns hidden index j = b*8+w and
// computes all 4 gate rows for j. w_hh in registers (128 fp32/lane).
//
// Inter-SM sync = tagged-h dataflow staged through SMEM (R5 structure):
//   phase A: poll h[0:512] (one v2.u64/thread) -> stage -> bar
//   GEMV half0
//   phase B: FRESH poll h[512:1024] -> stage -> bar
//   GEMV half1 -> reduce -> epilogue -> publish
// Phase-A wait: bounded dependent-reload spin (6 tries, RT-paced) to catch
// the producer straggler spread without paying the ~1us nanosleep quantum,
// then the VALIDATED sleep-always loop as fallback. Phase B first check
// nearly always hits (publishes are ~2000cyc old by then).
__global__ __launch_bounds__(256, 1)
void lstm_scan(const float* __restrict__ w_hh, int ysel, int layer)
{
    float* y_out = (ysel == 1) ? g_yA : g_yB;

    __shared__ __align__(16) float sm_h[2][HID];   // double-buffered staged h

    const int tid  = threadIdx.x;
    const int lane = tid & 31;
    const int warp = tid >> 5;
    const int j    = blockIdx.x * 8 + warp;    // 0..1023
    const unsigned tagbase = (unsigned)(layer * S_LEN + 1);  // never 0

    // this warp's w_hh slice in registers: w[gate][it] covers
    // k = it*128 + lane*4 .. +3, packed as two f32x2.
    unsigned long long w[4][8][2];
#pragma unroll
    for (int g = 0; g < 4; ++g)
#pragma unroll
        for (int it = 0; it < 8; ++it) {
            union { float4 f4; unsigned long long u[2]; } t;
            t.f4 = *(const float4*)(w_hh + (size_t)(g * HID + j) * HID
                                    + it * 128 + lane * 4);
            w[g][it][0] = t.u[0];
            w[g][it][1] = t.u[1];
        }

    float c = 0.0f;  // cell state (redundant in all lanes)

    // gates prefetch pipeline, 2 steps deep. Warp-uniform float4 load:
    // every lane gets all 4 gate values for its j (same 16B sector).
    const float4* gbase = (const float4*)g_gates + j;   // stride G4/4 per step
    float4 gq  = __ldcg(gbase + (size_t)0 * HID);
    float4 gq1 = __ldcg(gbase + (size_t)1 * HID);

    for (int t = 0; t < S_LEN; ++t) {
        // prefetch gates for t+2
        float4 gq2 = make_float4(0.f, 0.f, 0.f, 0.f);
        if (t + 2 < S_LEN) gq2 = __ldcg(gbase + (size_t)(t + 2) * HID);

        const int par = (t - 1) & 1;
        const unsigned tb = tagbase + (unsigned)(t - 1);
        // thread tid stages j = 2*tid and j = 2*tid+1 per phase
        const ulonglong2* pA = (const ulonglong2*)(g_hx + par * HID) + tid;
        const ulonglong2* pB = pA + 256;

        unsigned long long a0 = 0, a1 = 0, a2 = 0, a3 = 0;

        if (t > 0) {
            // ---- phase A: stage h[0:512] -------------------------------
            ulonglong2 v = ldcg16(pA);
            int spins = 0;
            while ((unsigned)(v.x >> 32) != tb || (unsigned)(v.y >> 32) != tb) {
                if (spins >= 6) __nanosleep(40);   // validated fallback
                ++spins;
                v = ldcg16(pA);                    // RT-paced dependent reload
            }
            sm_h[par][2 * tid]     = __uint_as_float((unsigned)v.x);
            sm_h[par][2 * tid + 1] = __uint_as_float((unsigned)v.y);
        }
        __syncthreads();

        if (t > 0) {
            // ---- GEMV half0 (k = 0..511) while half1 finishes landing ---
            const float* hs = sm_h[par];
#pragma unroll
            for (int it = 0; it < 4; ++it) {
                union { float4 f4; unsigned long long u[2]; } hv;
                hv.f4 = *(const float4*)(hs + it * 128 + lane * 4);
                ffma2(a0, hv.u[0], w[0][it][0]); ffma2(a0, hv.u[1], w[0][it][1]);
                ffma2(a1, hv.u[0], w[1][it][0]); ffma2(a1, hv.u[1], w[1][it][1]);
                ffma2(a2, hv.u[0], w[2][it][0]); ffma2(a2, hv.u[1], w[2][it][1]);
                ffma2(a3, hv.u[0], w[3][it][0]); ffma2(a3, hv.u[1], w[3][it][1]);
            }
            // ---- phase B: FRESH poll (publishes are old by now) ---------
            ulonglong2 v = ldcg16(pB);
            while ((unsigned)(v.x >> 32) != tb || (unsigned)(v.y >> 32) != tb) {
                __nanosleep(40);
                v = ldcg16(pB);
            }
            sm_h[par][512 + 2 * tid] = __uint_as_float((unsigned)v.x);
            sm_h[par][513 + 2 * tid] = __uint_as_float((unsigned)v.y);
        }
        __syncthreads();

        if (t > 0) {
            // ---- GEMV half1 (k = 512..1023) ----
            const float* hs = sm_h[par];
#pragma unroll
            for (int it = 4; it < 8; ++it) {
                union { float4 f4; unsigned long long u[2]; } hv;
                hv.f4 = *(const float4*)(hs + it * 128 + lane * 4);
                ffma2(a0, hv.u[0], w[0][it][0]); ffma2(a0, hv.u[1], w[0][it][1]);
                ffma2(a1, hv.u[0], w[1][it][0]); ffma2(a1, hv.u[1], w[1][it][1]);
                ffma2(a2, hv.u[0], w[2][it][0]); ffma2(a2, hv.u[1], w[2][it][1]);
                ffma2(a3, hv.u[0], w[3][it][0]); ffma2(a3, hv.u[1], w[3][it][1]);
            }
        }

        float2 p;
        p = unpack2(a0); float si = p.x + p.y;
        p = unpack2(a1); float sf = p.x + p.y;
        p = unpack2(a2); float sg = p.x + p.y;
        p = unpack2(a3); float so = p.x + p.y;
#pragma unroll
        for (int off = 16; off; off >>= 1) {
            si += __shfl_xor_sync(0xffffffffu, si, off);
            sf += __shfl_xor_sync(0xffffffffu, sf, off);
            sg += __shfl_xor_sync(0xffffffffu, sg, off);
            so += __shfl_xor_sync(0xffffffffu, so, off);
        }
        // butterfly left full sums in every lane; all lanes compute the
        // epilogue redundantly (no broadcast shuffles on the chain)
        float i_  = sigmoidf_(si + gq.x);
        float f_  = sigmoidf_(sf + gq.y);
        float gg_ = tanhf_  (sg + gq.z);
        float o_  = sigmoidf_(so + gq.w);
        c = f_ * c + i_ * gg_;
        float hn = o_ * tanhf_(c);
        if (lane == 0) {
            // publish {tag|value} as ONE atomic u64 — the inter-SM sync
            unsigned long long pub =
                ((unsigned long long)(tagbase + (unsigned)t) << 32)
                | (unsigned long long)__float_as_uint(hn);
            stcg8(&g_hx[(t & 1) * HID + j], pub);
            y_out[(size_t)t * HID + j] = hn;
        }
        gq = gq1; gq1 = gq2;
    }
}

// ---------------- final FC: out = h_last . fc_w + fc_b ---------------------
__global__ void fc_kernel(const float* __restrict__ w,
                          const float* __restrict__ b,
                          float* __restrict__ out)
{
    const float* h = g_yB + (size_t)(S_LEN - 1) * HID;
    const int tid = threadIdx.x;
    float s = 0.0f;
    for (int k = tid; k < HID; k += 256) s += h[k] * w[k];
#pragma unroll
    for (int off = 16; off; off >>= 1) s += __shfl_xor_sync(0xffffffffu, s, off);
    __shared__ float red[8];
    if ((tid & 31) == 0) red[tid >> 5] = s;
    __syncthreads();
    if (tid == 0) {
        float tot = 0.0f;
#pragma unroll
        for (int i = 0; i < 8; ++i) tot += red[i];
        out[0] = tot + b[0];
    }
}

// ---------------- launch ----------------------------------------------------
extern "C" void kernel_launch(void* const* d_in, const int* in_sizes, int n_in,
                              void* d_out, int out_size)
{
    (void)in_sizes; (void)n_in; (void)out_size;
    const float* seq   = (const float*)d_in[0];
    const float* w_ih0 = (const float*)d_in[1];
    const float* w_hh0 = (const float*)d_in[2];
    const float* b0    = (const float*)d_in[3];
    const float* w_ih1 = (const float*)d_in[4];
    const float* w_hh1 = (const float*)d_in[5];
    const float* b1    = (const float*)d_in[6];
    const float* w_ih2 = (const float*)d_in[7];
    const float* w_hh2 = (const float*)d_in[8];
    const float* b2    = (const float*)d_in[9];
    const float* w_ih3 = (const float*)d_in[10];
    const float* w_hh3 = (const float*)d_in[11];
    const float* b3    = (const float*)d_in[12];
    const float* fc_w  = (const float*)d_in[13];
    const float* fc_b  = (const float*)d_in[14];
    float* out = (float*)d_out;

    dim3 ggrid(G4 / 128, S_LEN / 128);

    // layer 0
    gemm_xwt<<<ggrid, 256>>>(seq, 0, w_ih0, b0, 256);
    lstm_scan<<<128, 256>>>(w_hh0, 1, 0);   // -> g_yA
    // layer 1
    gemm_xwt<<<ggrid, 256>>>(nullptr, 1, w_ih1, b1, HID);
    lstm_scan<<<128, 256>>>(w_hh1, 2, 1);   // -> g_yB
    // layer 2
    gemm_xwt<<<ggrid, 256>>>(nullptr, 2, w_ih2, b2, HID);
    lstm_scan<<<128, 256>>>(w_hh2, 1, 2);   // -> g_yA
    // layer 3
    gemm_xwt<<<ggrid, 256>>>(nullptr, 1, w_ih3, b3, HID);
    lstm_scan<<<128, 256>>>(w_hh3, 2, 3);   // -> g_yB
    // head
    fc_kernel<<<1, 256>>>(fc_w, fc_b, out);
}

// round 12
// speedup vs baseline: 2.4269x; 1.0728x over previous
#include <cuda_runtime.h>
#include <cstdint>
#include <cstddef>

#define S_LEN 8192
#define HID   1024
#define G4    4096   // 4*HID

// ---------------- scratch (device globals: allocation-free) ----------------
// gates layout: [S][HID][4]  (4 gate values for hidden j contiguous)
__device__ float g_gates[(size_t)S_LEN * G4];   // 128 MB
__device__ float g_yA[(size_t)S_LEN * HID];     // 32 MB: layer outputs ping
__device__ float g_yB[(size_t)S_LEN * HID];     // 32 MB: layer outputs pong
// hidden state values, double-buffered by step parity (no tags: the epoch
// counters below carry ALL ordering)
__device__ __align__(16) float g_hv[2][HID];
// epoch counters: [replica 0..7][layer][t]. Producer block adds 1 to every
// replica after publishing its h slice (release); consumer warp w polls
// replica w (acquire) until it reaches 128. Replica planes are 128KB apart
// -> different L2 lines, no hot-line serialization.
__device__ unsigned g_ctr[8][4][S_LEN];         // 1 MB

// ---------------- packed f32x2 helpers (sm_103a FFMA2) ----------------
__device__ __forceinline__ void ffma2(unsigned long long& d,
                                      unsigned long long a,
                                      unsigned long long b) {
    asm("fma.rn.f32x2 %0, %1, %2, %0;" : "+l"(d) : "l"(a), "l"(b));
}
__device__ __forceinline__ unsigned long long pack2(float x, float y) {
    unsigned long long r;
    asm("mov.b64 %0, {%1, %2};" : "=l"(r)
        : "r"(__float_as_uint(x)), "r"(__float_as_uint(y)));
    return r;
}
__device__ __forceinline__ float2 unpack2(unsigned long long v) {
    unsigned int lo, hi;
    asm("mov.b64 {%0, %1}, %2;" : "=r"(lo), "=r"(hi) : "l"(v));
    float2 r; r.x = __uint_as_float(lo); r.y = __uint_as_float(hi);
    return r;
}

__device__ __forceinline__ float sigmoidf_(float x) {
    return __fdividef(1.0f, 1.0f + __expf(-x));
}
// fast, overflow-safe tanh: tanh(x) = sign(x) * (1-e)/(1+e), e = exp(-2|x|)
__device__ __forceinline__ float tanhf_(float x) {
    float e = __expf(-2.0f * fabsf(x));
    float r = __fdividef(1.0f - e, 1.0f + e);
    return copysignf(r, x);
}

// release/acquire epoch ops (the cooperative-groups grid-sync pattern)
__device__ __forceinline__ unsigned ldacq(const unsigned* p) {
    unsigned v;
    asm volatile("ld.acquire.gpu.global.u32 %0, [%1];" : "=r"(v) : "l"(p));
    return v;
}
__device__ __forceinline__ void redrel(unsigned* p) {
    asm volatile("red.release.gpu.global.add.u32 [%0], 1;" :: "l"(p) : "memory");
}

// ---------------- zero the epoch counters (fresh every replay) -------------
__global__ void zero_ctr_kernel() {
    int i = blockIdx.x * blockDim.x + threadIdx.x;
    if (i < 8 * 4 * S_LEN) ((unsigned*)g_ctr)[i] = 0u;
}

// ---------------- GEMM: gates[S][HID][4] = X[S,K] @ W[4H,K]^T + b ----------
// BM=BN=128, BK=16, 256 threads, 8x8 microtile, f32x2 packed FMAs.
__global__ __launch_bounds__(256)
void gemm_xwt(const float* __restrict__ Xext, int xsel,
              const float* __restrict__ W, const float* __restrict__ bias,
              int K)
{
    const float* X = (xsel == 0) ? Xext : (xsel == 1 ? g_yA : g_yB);

    __shared__ float a_s[16][128];
    __shared__ float b_s[16][128];

    const int tid = threadIdx.x;
    const int bm = blockIdx.y * 128;
    const int bn = blockIdx.x * 128;
    const int tx = tid & 15;   // 0..15 -> N
    const int ty = tid >> 4;   // 0..15 -> M

    unsigned long long acc[8][4];
#pragma unroll
    for (int i = 0; i < 8; ++i)
#pragma unroll
        for (int jp = 0; jp < 4; ++jp) acc[i][jp] = 0ull;

    for (int k0 = 0; k0 < K; k0 += 16) {
#pragma unroll
        for (int r = 0; r < 2; ++r) {
            int q   = tid + r * 256;      // 0..511 float4 slots
            int row = q >> 2;             // 0..127
            int kq  = (q & 3) << 2;       // 0,4,8,12
            float4 va = *(const float4*)(X + (size_t)(bm + row) * K + k0 + kq);
            a_s[kq + 0][row] = va.x; a_s[kq + 1][row] = va.y;
            a_s[kq + 2][row] = va.z; a_s[kq + 3][row] = va.w;
            float4 vb = *(const float4*)(W + (size_t)(bn + row) * K + k0 + kq);
            b_s[kq + 0][row] = vb.x; b_s[kq + 1][row] = vb.y;
            b_s[kq + 2][row] = vb.z; b_s[kq + 3][row] = vb.w;
        }
        __syncthreads();
#pragma unroll
        for (int kk = 0; kk < 16; ++kk) {
            float4 a0 = *(const float4*)&a_s[kk][ty * 8];
            float4 a1 = *(const float4*)&a_s[kk][ty * 8 + 4];
            float4 b0 = *(const float4*)&b_s[kk][tx * 8];
            float4 b1 = *(const float4*)&b_s[kk][tx * 8 + 4];
            unsigned long long bp0 = pack2(b0.x, b0.y);
            unsigned long long bp1 = pack2(b0.z, b0.w);
            unsigned long long bp2 = pack2(b1.x, b1.y);
            unsigned long long bp3 = pack2(b1.z, b1.w);
            float av[8] = {a0.x, a0.y, a0.z, a0.w, a1.x, a1.y, a1.z, a1.w};
#pragma unroll
            for (int i = 0; i < 8; ++i) {
                unsigned long long ap = pack2(av[i], av[i]);
                ffma2(acc[i][0], ap, bp0);
                ffma2(acc[i][1], ap, bp1);
                ffma2(acc[i][2], ap, bp2);
                ffma2(acc[i][3], ap, bp3);
            }
        }
        __syncthreads();
    }

    // epilogue: scatter into [S][HID][4] interleaved-gate layout
    const int gate = bn >> 10;          // constant per block (bn multiple of 128)
#pragma unroll
    for (int i = 0; i < 8; ++i) {
        size_t row = (size_t)(bm + ty * 8 + i);
#pragma unroll
        for (int jp = 0; jp < 4; ++jp) {
            int col = bn + tx * 8 + jp * 2;
            int jj  = col - (gate << 10);
            float2 v = unpack2(acc[i][jp]);
            g_gates[row * G4 + (size_t)jj * 4 + gate]       = v.x + bias[col];
            g_gates[row * G4 + (size_t)(jj + 1) * 4 + gate] = v.y + bias[col + 1];
        }
    }
}

// ---------------- persistent recurrent scan (one launch per layer) ---------
// 128 blocks x 8 warps; warp w of block b owns hidden index j = b*8+w and
// computes all 4 gate rows for j. w_hh in registers (128 fp32/lane).
//
// Inter-SM sync = release/acquire epoch counters (grid-sync pattern):
//   producer: st.cg h values -> bar.sync -> red.release.gpu on 8 replicas
//   consumer: warp w polls replica w with ld.acquire.gpu until ==128,
//             then ld.cg the bare h values (ordering carried by acquire).
// One wait segment per step; when the epoch flips, all consumers detect
// within ~1 L2 round trip. Bounded spin(8) then nanosleep(40) fallback.
__global__ __launch_bounds__(256, 1)
void lstm_scan(const float* __restrict__ w_hh, int ysel, int layer)
{
    float* y_out = (ysel == 1) ? g_yA : g_yB;

    __shared__ __align__(16) float sm_h[2][HID];   // double-buffered staged h

    const int tid  = threadIdx.x;
    const int lane = tid & 31;
    const int warp = tid >> 5;
    const int j    = blockIdx.x * 8 + warp;    // 0..1023

    // this warp's w_hh slice in registers: w[gate][it] covers
    // k = it*128 + lane*4 .. +3, packed as two f32x2.
    unsigned long long w[4][8][2];
#pragma unroll
    for (int g = 0; g < 4; ++g)
#pragma unroll
        for (int it = 0; it < 8; ++it) {
            union { float4 f4; unsigned long long u[2]; } t;
            t.f4 = *(const float4*)(w_hh + (size_t)(g * HID + j) * HID
                                    + it * 128 + lane * 4);
            w[g][it][0] = t.u[0];
            w[g][it][1] = t.u[1];
        }

    float c = 0.0f;  // cell state (redundant in all lanes)

    // gates prefetch pipeline, 2 steps deep. Warp-uniform float4 load:
    // every lane gets all 4 gate values for its j (same 16B sector).
    const float4* gbase = (const float4*)g_gates + j;   // stride G4/4 per step
    float4 gq  = __ldcg(gbase + (size_t)0 * HID);
    float4 gq1 = __ldcg(gbase + (size_t)1 * HID);

    for (int t = 0; t < S_LEN; ++t) {
        // prefetch gates for t+2
        float4 gq2 = make_float4(0.f, 0.f, 0.f, 0.f);
        if (t + 2 < S_LEN) gq2 = __ldcg(gbase + (size_t)(t + 2) * HID);

        const int par = (t - 1) & 1;

        if (t > 0) {
            // ---- wait for epoch(t-1): all lanes poll the warp's replica --
            const unsigned* cp = &g_ctr[warp][layer][t - 1];
            unsigned v = ldacq(cp);
            int spins = 0;
            while (v < 128u) {
                if (spins >= 8) __nanosleep(40);   // validated fallback
                ++spins;
                v = ldacq(cp);                     // RT-paced dependent reload
            }
            // ---- stage h(t-1): thread tid covers h[4*tid .. 4*tid+3] -----
            float4 hv = __ldcg((const float4*)&g_hv[par][4 * tid]);
            *(float4*)&sm_h[par][4 * tid] = hv;
        }
        __syncthreads();

        unsigned long long a0 = 0, a1 = 0, a2 = 0, a3 = 0;
        if (t > 0) {
            // ---- full GEMV (k = 0..1023) from SMEM ----
            const float* hs = sm_h[par];
#pragma unroll
            for (int it = 0; it < 8; ++it) {
                union { float4 f4; unsigned long long u[2]; } hv;
                hv.f4 = *(const float4*)(hs + it * 128 + lane * 4);
                ffma2(a0, hv.u[0], w[0][it][0]); ffma2(a0, hv.u[1], w[0][it][1]);
                ffma2(a1, hv.u[0], w[1][it][0]); ffma2(a1, hv.u[1], w[1][it][1]);
                ffma2(a2, hv.u[0], w[2][it][0]); ffma2(a2, hv.u[1], w[2][it][1]);
                ffma2(a3, hv.u[0], w[3][it][0]); ffma2(a3, hv.u[1], w[3][it][1]);
            }
        }

        float2 p;
        p = unpack2(a0); float si = p.x + p.y;
        p = unpack2(a1); float sf = p.x + p.y;
        p = unpack2(a2); float sg = p.x + p.y;
        p = unpack2(a3); float so = p.x + p.y;
#pragma unroll
        for (int off = 16; off; off >>= 1) {
            si += __shfl_xor_sync(0xffffffffu, si, off);
            sf += __shfl_xor_sync(0xffffffffu, sf, off);
            sg += __shfl_xor_sync(0xffffffffu, sg, off);
            so += __shfl_xor_sync(0xffffffffu, so, off);
        }
        // butterfly left full sums in every lane; all lanes compute the
        // epilogue redundantly (no broadcast shuffles on the chain)
        float i_  = sigmoidf_(si + gq.x);
        float f_  = sigmoidf_(sf + gq.y);
        float gg_ = tanhf_  (sg + gq.z);
        float o_  = sigmoidf_(so + gq.w);
        c = f_ * c + i_ * gg_;
        float hn = o_ * tanhf_(c);
        if (lane == 0) {
            __stcg(&g_hv[t & 1][j], hn);        // bare value publish
            y_out[(size_t)t * HID + j] = hn;
        }
        // ---- release epoch(t): bar orders ALL warps' publishes before the
        //      release-adds (CG grid-sync pattern) ------------------------
        __syncthreads();
        if (tid < 8) redrel(&g_ctr[tid][layer][t]);

        gq = gq1; gq1 = gq2;
    }
}

// ---------------- final FC: out = h_last . fc_w + fc_b ---------------------
__global__ void fc_kernel(const float* __restrict__ w,
                          const float* __restrict__ b,
                          float* __restrict__ out)
{
    const float* h = g_yB + (size_t)(S_LEN - 1) * HID;
    const int tid = threadIdx.x;
    float s = 0.0f;
    for (int k = tid; k < HID; k += 256) s += h[k] * w[k];
#pragma unroll
    for (int off = 16; off; off >>= 1) s += __shfl_xor_sync(0xffffffffu, s, off);
    __shared__ float red[8];
    if ((tid & 31) == 0) red[tid >> 5] = s;
    __syncthreads();
    if (tid == 0) {
        float tot = 0.0f;
#pragma unroll
        for (int i = 0; i < 8; ++i) tot += red[i];
        out[0] = tot + b[0];
    }
}

// ---------------- launch ----------------------------------------------------
extern "C" void kernel_launch(void* const* d_in, const int* in_sizes, int n_in,
                              void* d_out, int out_size)
{
    (void)in_sizes; (void)n_in; (void)out_size;
    const float* seq   = (const float*)d_in[0];
    const float* w_ih0 = (const float*)d_in[1];
    const float* w_hh0 = (const float*)d_in[2];
    const float* b0    = (const float*)d_in[3];
    const float* w_ih1 = (const float*)d_in[4];
    const float* w_hh1 = (const float*)d_in[5];
    const float* b1    = (const float*)d_in[6];
    const float* w_ih2 = (const float*)d_in[7];
    const float* w_hh2 = (const float*)d_in[8];
    const float* b2    = (const float*)d_in[9];
    const float* w_ih3 = (const float*)d_in[10];
    const float* w_hh3 = (const float*)d_in[11];
    const float* b3    = (const float*)d_in[12];
    const float* fc_w  = (const float*)d_in[13];
    const float* fc_b  = (const float*)d_in[14];
    float* out = (float*)d_out;

    dim3 ggrid(G4 / 128, S_LEN / 128);

    // fresh epoch counters every replay (overlaps with nothing critical)
    zero_ctr_kernel<<<1024, 256>>>();

    // layer 0
    gemm_xwt<<<ggrid, 256>>>(seq, 0, w_ih0, b0, 256);
    lstm_scan<<<128, 256>>>(w_hh0, 1, 0);   // -> g_yA
    // layer 1
    gemm_xwt<<<ggrid, 256>>>(nullptr, 1, w_ih1, b1, HID);
    lstm_scan<<<128, 256>>>(w_hh1, 2, 1);   // -> g_yB
    // layer 2
    gemm_xwt<<<ggrid, 256>>>(nullptr, 2, w_ih2, b2, HID);
    lstm_scan<<<128, 256>>>(w_hh2, 1, 2);   // -> g_yA
    // layer 3
    gemm_xwt<<<ggrid, 256>>>(nullptr, 1, w_ih3, b3, HID);
    lstm_scan<<<128, 256>>>(w_hh3, 2, 3);   // -> g_yB
    // head
    fc_kernel<<<1, 256>>>(fc_w, fc_b, out);
}